// round 12
// baseline (speedup 1.0000x reference)
#include <cuda_runtime.h>
#include <stdint.h>

// ===========================================================================
// JAX threefry2x32 (exact)
// ===========================================================================
static void threefry2x32_host(
    uint32_t k0, uint32_t k1, uint32_t x0, uint32_t x1,
    uint32_t& o0, uint32_t& o1)
{
    uint32_t ks2 = k0 ^ k1 ^ 0x1BD11BDAu;
    x0 += k0; x1 += k1;
#define TF_RNDH(R) { x0 += x1; x1 = (x1 << (R)) | (x1 >> (32 - (R))); x1 ^= x0; }
    TF_RNDH(13) TF_RNDH(15) TF_RNDH(26) TF_RNDH(6)   x0 += k1;  x1 += ks2 + 1u;
    TF_RNDH(17) TF_RNDH(29) TF_RNDH(16) TF_RNDH(24)  x0 += ks2; x1 += k0  + 2u;
    TF_RNDH(13) TF_RNDH(15) TF_RNDH(26) TF_RNDH(6)   x0 += k0;  x1 += k1  + 3u;
    TF_RNDH(17) TF_RNDH(29) TF_RNDH(16) TF_RNDH(24)  x0 += k1;  x1 += ks2 + 4u;
    TF_RNDH(13) TF_RNDH(15) TF_RNDH(26) TF_RNDH(6)   x0 += ks2; x1 += k0  + 5u;
#undef TF_RNDH
    o0 = x0; o1 = x1;
}

// keep-decision for flat element e: partitionable threefry counter (0, e),
// XOR-fold, uniform<0.8f as EXACT integer compare: bits < 0xCCCCCE00 (R9-verified)
__device__ __forceinline__ uint32_t tf_keep(uint32_t k0, uint32_t k1, uint32_t ks2,
                                            uint32_t e)
{
    uint32_t x0 = k0, x1 = e + k1;
#define TF_RND(R) { x0 += x1; x1 = __funnelshift_l(x1, x1, R); x1 ^= x0; }
    TF_RND(13) TF_RND(15) TF_RND(26) TF_RND(6)   x0 += k1;  x1 += ks2 + 1u;
    TF_RND(17) TF_RND(29) TF_RND(16) TF_RND(24)  x0 += ks2; x1 += k0  + 2u;
    TF_RND(13) TF_RND(15) TF_RND(26) TF_RND(6)   x0 += k0;  x1 += k1  + 3u;
    TF_RND(17) TF_RND(29) TF_RND(16) TF_RND(24)  x0 += k1;  x1 += ks2 + 4u;
    TF_RND(13) TF_RND(15) TF_RND(26) TF_RND(6)   x0 += ks2; x1 += k0  + 5u;
#undef TF_RND
    return ((x0 ^ x1) < 0xCCCCCE00u) ? 1u : 0u;
}

// ===========================================================================
// Tensor-core primitives (baseline PTX — valid on compute_103 non-'a')
// ===========================================================================
__device__ __forceinline__ uint32_t smem_u32(const void* p) {
    uint32_t a;
    asm("{ .reg .u64 t; cvta.to.shared.u64 t, %1; cvt.u32.u64 %0, t; }"
        : "=r"(a) : "l"(p));
    return a;
}
__device__ __forceinline__ void ldm4(uint32_t addr,
    uint32_t& r0, uint32_t& r1, uint32_t& r2, uint32_t& r3)
{
    asm volatile("ldmatrix.sync.aligned.m8n8.x4.shared.b16 {%0,%1,%2,%3}, [%4];"
                 : "=r"(r0), "=r"(r1), "=r"(r2), "=r"(r3) : "r"(addr));
}
// tf32 m16n8k8: fragment layout = fp32-word view of the bf16 m16n8k16 layout,
// so ldmatrix.b16 addressing carries over unchanged.
__device__ __forceinline__ void mma1688(float* d,
    uint32_t a0, uint32_t a1, uint32_t a2, uint32_t a3,
    uint32_t b0, uint32_t b1)
{
    asm volatile(
        "mma.sync.aligned.m16n8k8.row.col.f32.tf32.tf32.f32 "
        "{%0,%1,%2,%3}, {%4,%5,%6,%7}, {%8,%9}, {%0,%1,%2,%3};"
        : "+f"(d[0]), "+f"(d[1]), "+f"(d[2]), "+f"(d[3])
        : "r"(a0), "r"(a1), "r"(a2), "r"(a3), "r"(b0), "r"(b1));
}
// fp32 -> tf32 round-to-nearest (RNA; truncation would bias ~1e-3 — must round)
__device__ __forceinline__ uint32_t f2tf32(float f) {
    uint32_t u;
    asm("cvt.rna.tf32.f32 %0, %1;" : "=r"(u) : "f"(f));
    return u;
}
__device__ __forceinline__ uint4 cvt4(float4 v) {
    return make_uint4(f2tf32(v.x), f2tf32(v.y), f2tf32(v.z), f2tf32(v.w));
}

// ===========================================================================
// Grouped fused kernel: ALL 8 types in ONE launch.
// Block 128x128, 256 threads = 8 warps, warp tile 32x64.
// tf32 GEMM + bias + partitionable-threefry inverted dropout.
// RNG: 64 keep-bits per thread, generated in 8 chunks of 8 hashes spread
// UNIFORMLY across all k-tiles (chunk range [kt*8/ksteps, (kt+1)*8/ksteps))
// so the alu pipe load is flat instead of bursty (R11: alu=60% bound).
// ===========================================================================
#define RSW 36   // smem row stride in fp32 words (144 bytes)

struct Entry {
    const float* x;
    const float* W;
    const float* bias;
    float*       out;
    int N, C, ksteps, bstart;
    uint32_t k0, k1;
};
struct Params { Entry e[8]; };

__global__ __launch_bounds__(256, 2) void fused_all(Params p)
{
    __shared__ __align__(16) uint32_t Asm[128 * RSW];
    __shared__ __align__(16) uint32_t Bsm[128 * RSW];

    const int bid = blockIdx.x;
    int t = 0;
#pragma unroll
    for (int i = 1; i < 8; i++)
        if (bid >= p.e[i].bstart) t = i;

    const float* __restrict__ x    = p.e[t].x;
    const float* __restrict__ W    = p.e[t].W;
    const float* __restrict__ bias = p.e[t].bias;
    float*       __restrict__ out  = p.e[t].out;
    const int N      = p.e[t].N;
    const int C      = p.e[t].C;
    const int ksteps = p.e[t].ksteps;
    const uint32_t k0 = p.e[t].k0, k1 = p.e[t].k1;
    const uint32_t ks2 = k0 ^ k1 ^ 0x1BD11BDAu;
    const int base = (bid - p.e[t].bstart) * 128;

    const int tid  = threadIdx.x;
    const int lane = tid & 31;
    const int warp = tid >> 5;
    const int wm   = warp & 3;
    const int wn   = warp >> 2;

    const uint32_t uA = smem_u32(Asm), uB = smem_u32(Bsm);

    const int r16  = lane & 15;
    const int hc16 = (lane >> 4) << 4;
    const int rowq = lane >> 2;
    const int colq = (lane & 3) * 2;

    float acc[2][8][4];
#pragma unroll
    for (int i = 0; i < 2; i++)
#pragma unroll
        for (int j = 0; j < 8; j++)
#pragma unroll
            for (int q = 0; q < 4; q++) acc[i][j][q] = 0.0f;

    uint32_t kmask0 = 0, kmask1 = 0;

    for (int kt = 0; kt < ksteps; kt++) {
        const int kb = kt * 32;
        // ---- load fp32, tf32-round, store to smem ----
#pragma unroll
        for (int it = 0; it < 4; it++) {
            int idx = tid + it * 256;
            int row = idx >> 3;
            int q   = idx & 7;
            int soff = row * RSW + q * 4;

            int gr = base + row;
            float4 va = make_float4(0.f, 0.f, 0.f, 0.f);
            if (gr < N) va = *(const float4*)(x + (long)gr * C + kb + q * 4);
            *(uint4*)(Asm + soff) = cvt4(va);

            float4 vw = *(const float4*)(W + (long)row * C + kb + q * 4);
            *(uint4*)(Bsm + soff) = cvt4(vw);
        }
        __syncthreads();

        // ---- dropout mask: chunks of 8 hashes, spread over all k-tiles ----
        // global chunk range for this tile: [kt*8/ksteps, (kt+1)*8/ksteps)
        {
            int c0 = (kt * 8) / ksteps;
            int c1 = ((kt + 1) * 8) / ksteps;
            for (int ch = c0; ch < c1; ch++) {
                uint32_t m8 = 0;
#pragma unroll
                for (int j = 0; j < 8; j++) {
                    int i  = ch * 8 + j;                   // mask bit 0..63
                    int am = i >> 5;
                    int an = (i >> 2) & 7, rp = (i >> 1) & 1, cp = i & 1;
                    uint32_t row = (uint32_t)(base + wm * 32 + am * 16 + rowq + rp * 8);
                    uint32_t col = (uint32_t)(wn * 64 + an * 8 + colq + cp);
                    m8 |= tf_keep(k0, k1, ks2, row * 128u + col) << j;
                }
                int sh = (ch & 3) * 8;
                if (ch < 4) kmask0 |= m8 << sh;
                else        kmask1 |= m8 << sh;
            }
        }

        // ---- MMA: 4 chunks of 8 fp32-k ----
#pragma unroll
        for (int c8 = 0; c8 < 4; c8++) {
            const int coff = c8 * 32 + hc16;

            uint32_t ah[2][4];
#pragma unroll
            for (int am = 0; am < 2; am++)
                ldm4(uA + (uint32_t)((wm * 32 + am * 16 + r16) * 144 + coff),
                     ah[am][0], ah[am][1], ah[am][2], ah[am][3]);

            uint32_t b[4][4];
#pragma unroll
            for (int pg = 0; pg < 4; pg++)
                ldm4(uB + (uint32_t)((wn * 64 + pg * 16 + r16) * 144 + coff),
                     b[pg][0], b[pg][1], b[pg][2], b[pg][3]);

#pragma unroll
            for (int am = 0; am < 2; am++)
#pragma unroll
                for (int pg = 0; pg < 4; pg++) {
                    mma1688(acc[am][2 * pg],     ah[am][0], ah[am][1], ah[am][2], ah[am][3], b[pg][0], b[pg][2]);
                    mma1688(acc[am][2 * pg + 1], ah[am][0], ah[am][1], ah[am][2], ah[am][3], b[pg][1], b[pg][3]);
                }
        }
        __syncthreads();
    }

    // ---- epilogue: bias + masked scale + store ----
    // mask bit i = (am*32) + an*4 + rp*2 + cp (matches generation order)
#pragma unroll
    for (int am = 0; am < 2; am++) {
        int row0 = base + wm * 32 + am * 16 + rowq;
        uint32_t m = (am == 0) ? kmask0 : kmask1;
#pragma unroll
        for (int an = 0; an < 8; an++) {
            int col = wn * 64 + an * 8 + colq;
            float b0 = __ldg(bias + col);
            float b1 = __ldg(bias + col + 1);
#pragma unroll
            for (int rp = 0; rp < 2; rp++) {
                int row = row0 + rp * 8;
                if (row < N) {
                    int i0 = an * 4 + rp * 2;
                    uint32_t bit0 = (m >> i0) & 1u;
                    uint32_t bit1 = (m >> (i0 + 1)) & 1u;
                    float y0 = acc[am][an][rp * 2 + 0] + b0;
                    float y1 = acc[am][an][rp * 2 + 1] + b1;
                    float2 v;
                    v.x = bit0 ? y0 * 1.25f : 0.0f;
                    v.y = bit1 ? y1 * 1.25f : 0.0f;
                    *(float2*)(out + (size_t)row * 128 + col) = v;
                }
            }
        }
    }
}

// ===========================================================================
// Launch: ONE grouped kernel. Inputs interleaved (x_t, W_t, b_t) x 8; detect.
// ===========================================================================
static const int C_TAB[8] = {128, 256, 64, 128, 192, 96, 160, 128};

extern "C" void kernel_launch(void* const* d_in, const int* in_sizes, int n_in,
                              void* d_out, int out_size)
{
    (void)n_in; (void)out_size;
    const bool interleaved = (in_sizes[1] == 128 * C_TAB[0]);

    Params p;
    size_t off = 0;
    int bstart = 0;
    for (int t = 0; t < 8; t++) {
        const int C = C_TAB[t];
        const int xi = interleaved ? (3 * t)     : t;
        const int wi = interleaved ? (3 * t + 1) : (8 + t);
        const int bi = interleaved ? (3 * t + 2) : (16 + t);
        const int N  = in_sizes[xi] / C;

        uint32_t fk0, fk1;
        threefry2x32_host(0u, 42u, 0u, (uint32_t)t, fk0, fk1);

        p.e[t].x      = (const float*)d_in[xi];
        p.e[t].W      = (const float*)d_in[wi];
        p.e[t].bias   = (const float*)d_in[bi];
        p.e[t].out    = (float*)d_out + off;
        p.e[t].N      = N;
        p.e[t].C      = C;
        p.e[t].ksteps = C / 32;
        p.e[t].bstart = bstart;
        p.e[t].k0     = fk0;
        p.e[t].k1     = fk1;

        bstart += (N + 127) / 128;
        off += (size_t)N * 128;
    }

    fused_all<<<bstart, 256>>>(p);
}

// round 13
// speedup vs baseline: 1.0703x; 1.0703x over previous
#include <cuda_runtime.h>
#include <stdint.h>

// ===========================================================================
// JAX threefry2x32 (exact)
// ===========================================================================
static void threefry2x32_host(
    uint32_t k0, uint32_t k1, uint32_t x0, uint32_t x1,
    uint32_t& o0, uint32_t& o1)
{
    uint32_t ks2 = k0 ^ k1 ^ 0x1BD11BDAu;
    x0 += k0; x1 += k1;
#define TF_RNDH(R) { x0 += x1; x1 = (x1 << (R)) | (x1 >> (32 - (R))); x1 ^= x0; }
    TF_RNDH(13) TF_RNDH(15) TF_RNDH(26) TF_RNDH(6)   x0 += k1;  x1 += ks2 + 1u;
    TF_RNDH(17) TF_RNDH(29) TF_RNDH(16) TF_RNDH(24)  x0 += ks2; x1 += k0  + 2u;
    TF_RNDH(13) TF_RNDH(15) TF_RNDH(26) TF_RNDH(6)   x0 += k0;  x1 += k1  + 3u;
    TF_RNDH(17) TF_RNDH(29) TF_RNDH(16) TF_RNDH(24)  x0 += k1;  x1 += ks2 + 4u;
    TF_RNDH(13) TF_RNDH(15) TF_RNDH(26) TF_RNDH(6)   x0 += ks2; x1 += k0  + 5u;
#undef TF_RNDH
    o0 = x0; o1 = x1;
}

// keep-decision for flat element e: partitionable threefry counter (0, e),
// XOR-fold, uniform<0.8f as EXACT integer compare: bits < 0xCCCCCE00 (R9-verified)
__device__ __forceinline__ uint32_t tf_keep(uint32_t k0, uint32_t k1, uint32_t ks2,
                                            uint32_t e)
{
    uint32_t x0 = k0, x1 = e + k1;
#define TF_RND(R) { x0 += x1; x1 = __funnelshift_l(x1, x1, R); x1 ^= x0; }
    TF_RND(13) TF_RND(15) TF_RND(26) TF_RND(6)   x0 += k1;  x1 += ks2 + 1u;
    TF_RND(17) TF_RND(29) TF_RND(16) TF_RND(24)  x0 += ks2; x1 += k0  + 2u;
    TF_RND(13) TF_RND(15) TF_RND(26) TF_RND(6)   x0 += k0;  x1 += k1  + 3u;
    TF_RND(17) TF_RND(29) TF_RND(16) TF_RND(24)  x0 += k1;  x1 += ks2 + 4u;
    TF_RND(13) TF_RND(15) TF_RND(26) TF_RND(6)   x0 += ks2; x1 += k0  + 5u;
#undef TF_RND
    return ((x0 ^ x1) < 0xCCCCCE00u) ? 1u : 0u;
}

// ===========================================================================
// Tensor-core primitives (baseline PTX — valid on compute_103 non-'a')
// ===========================================================================
__device__ __forceinline__ uint32_t smem_u32(const void* p) {
    uint32_t a;
    asm("{ .reg .u64 t; cvta.to.shared.u64 t, %1; cvt.u32.u64 %0, t; }"
        : "=r"(a) : "l"(p));
    return a;
}
__device__ __forceinline__ void ldm4(uint32_t addr,
    uint32_t& r0, uint32_t& r1, uint32_t& r2, uint32_t& r3)
{
    asm volatile("ldmatrix.sync.aligned.m8n8.x4.shared.b16 {%0,%1,%2,%3}, [%4];"
                 : "=r"(r0), "=r"(r1), "=r"(r2), "=r"(r3) : "r"(addr));
}
// tf32 m16n8k8: fragment layout = fp32-word view of bf16 m16n8k16 layout.
__device__ __forceinline__ void mma1688(float* d,
    uint32_t a0, uint32_t a1, uint32_t a2, uint32_t a3,
    uint32_t b0, uint32_t b1)
{
    asm volatile(
        "mma.sync.aligned.m16n8k8.row.col.f32.tf32.tf32.f32 "
        "{%0,%1,%2,%3}, {%4,%5,%6,%7}, {%8,%9}, {%0,%1,%2,%3};"
        : "+f"(d[0]), "+f"(d[1]), "+f"(d[2]), "+f"(d[3])
        : "r"(a0), "r"(a1), "r"(a2), "r"(a3), "r"(b0), "r"(b1));
}
// fp32 -> tf32 round-to-nearest (RNA; truncation would bias ~1e-3)
__device__ __forceinline__ uint32_t f2tf32(float f) {
    uint32_t u;
    asm("cvt.rna.tf32.f32 %0, %1;" : "=r"(u) : "f"(f));
    return u;
}
__device__ __forceinline__ uint4 cvt4(float4 v) {
    return make_uint4(f2tf32(v.x), f2tf32(v.y), f2tf32(v.z), f2tf32(v.w));
}

// ===========================================================================
// Grouped fused kernel, ALL 8 types in ONE launch.
// CTA tile 128 rows x 64 cols (col-half picked by local block parity) so that
// acc = 32 regs/thread and 3 CTAs/SM fit (R11 was reg-capped at 2 CTAs,
// issue 57.6%). 256 threads = 8 warps, warp tile 32x32.
// tf32 GEMM + bias + partitionable-threefry inverted dropout; 32 keep-bits
// per thread as two fully-unrolled 16-hash bursts in k-tiles 0/1 (R11-style;
// the R12 runtime-bounded spread regressed).
// ===========================================================================
#define RSW 36   // smem row stride in fp32 words (144 bytes)

struct Entry {
    const float* x;
    const float* W;
    const float* bias;
    float*       out;
    int N, C, ksteps, bstart;
    uint32_t k0, k1;
};
struct Params { Entry e[8]; };

__global__ __launch_bounds__(256, 3) void fused_all(Params p)
{
    __shared__ __align__(16) uint32_t Asm[128 * RSW];
    __shared__ __align__(16) uint32_t Bsm[64 * RSW];

    const int bid = blockIdx.x;
    int t = 0;
#pragma unroll
    for (int i = 1; i < 8; i++)
        if (bid >= p.e[i].bstart) t = i;

    const float* __restrict__ x    = p.e[t].x;
    const float* __restrict__ W    = p.e[t].W;
    const float* __restrict__ bias = p.e[t].bias;
    float*       __restrict__ out  = p.e[t].out;
    const int N      = p.e[t].N;
    const int C      = p.e[t].C;
    const int ksteps = p.e[t].ksteps;
    const uint32_t k0 = p.e[t].k0, k1 = p.e[t].k1;
    const uint32_t ks2 = k0 ^ k1 ^ 0x1BD11BDAu;

    const int local = bid - p.e[t].bstart;
    const int base  = (local >> 1) * 128;      // row base
    const int colh  = (local & 1) * 64;        // col half: 0 or 64

    const int tid  = threadIdx.x;
    const int lane = tid & 31;
    const int warp = tid >> 5;
    const int wm   = warp & 3;                 // row group: wm*32
    const int wn   = warp >> 2;                // col group within half: wn*32

    const uint32_t uA = smem_u32(Asm), uB = smem_u32(Bsm);

    const int r16  = lane & 15;
    const int hc16 = (lane >> 4) << 4;
    const int rowq = lane >> 2;
    const int colq = (lane & 3) * 2;
    const int colbase = colh + wn * 32;

    float acc[2][4][4];
#pragma unroll
    for (int i = 0; i < 2; i++)
#pragma unroll
        for (int j = 0; j < 4; j++)
#pragma unroll
            for (int q = 0; q < 4; q++) acc[i][j][q] = 0.0f;

    uint32_t kmask = 0;

    for (int kt = 0; kt < ksteps; kt++) {
        const int kb = kt * 32;
        // ---- A tile: 128 rows x 32 k (4 float4/thread) ----
#pragma unroll
        for (int it = 0; it < 4; it++) {
            int idx = tid + it * 256;
            int row = idx >> 3;
            int q   = idx & 7;
            int gr  = base + row;
            float4 va = make_float4(0.f, 0.f, 0.f, 0.f);
            if (gr < N) va = *(const float4*)(x + (long)gr * C + kb + q * 4);
            *(uint4*)(Asm + row * RSW + q * 4) = cvt4(va);
        }
        // ---- B tile: 64 W-rows (this col half) x 32 k (2 float4/thread) ----
#pragma unroll
        for (int it = 0; it < 2; it++) {
            int idx = tid + it * 256;          // 0..511
            int row = idx >> 3;                // 0..63
            int q   = idx & 7;
            float4 vw = *(const float4*)(W + (long)(colh + row) * C + kb + q * 4);
            *(uint4*)(Bsm + row * RSW + q * 4) = cvt4(vw);
        }
        __syncthreads();

        // ---- dropout mask burst: 16 keep-bits in k-tiles 0 and 1 ----
        if (kt < 2) {
            const int am = kt;                 // 16-row group
            uint32_t m = 0;
#pragma unroll
            for (int ii = 0; ii < 16; ii++) {
                int an = ii >> 2, rp = (ii >> 1) & 1, cp = ii & 1;
                uint32_t row = (uint32_t)(base + wm * 32 + am * 16 + rowq + rp * 8);
                uint32_t col = (uint32_t)(colbase + an * 8 + colq + cp);
                m |= tf_keep(k0, k1, ks2, row * 128u + col) << ii;
            }
            kmask |= m << (kt * 16);
        }

        // ---- MMA: 4 chunks of 8 fp32-k ----
#pragma unroll
        for (int c8 = 0; c8 < 4; c8++) {
            const int coff = c8 * 32 + hc16;

            uint32_t ah[2][4];
#pragma unroll
            for (int am = 0; am < 2; am++)
                ldm4(uA + (uint32_t)((wm * 32 + am * 16 + r16) * 144 + coff),
                     ah[am][0], ah[am][1], ah[am][2], ah[am][3]);

            uint32_t b[2][4];
#pragma unroll
            for (int pg = 0; pg < 2; pg++)
                ldm4(uB + (uint32_t)((wn * 32 + pg * 16 + r16) * 144 + coff),
                     b[pg][0], b[pg][1], b[pg][2], b[pg][3]);

#pragma unroll
            for (int am = 0; am < 2; am++)
#pragma unroll
                for (int pg = 0; pg < 2; pg++) {
                    mma1688(acc[am][2 * pg],     ah[am][0], ah[am][1], ah[am][2], ah[am][3], b[pg][0], b[pg][2]);
                    mma1688(acc[am][2 * pg + 1], ah[am][0], ah[am][1], ah[am][2], ah[am][3], b[pg][1], b[pg][3]);
                }
        }
        __syncthreads();
    }

    // ---- epilogue: bias + masked scale + store ----
    // mask bit i = am*16 + an*4 + rp*2 + cp (matches generation)
#pragma unroll
    for (int am = 0; am < 2; am++) {
        int row0 = base + wm * 32 + am * 16 + rowq;
#pragma unroll
        for (int an = 0; an < 4; an++) {
            int col = colbase + an * 8 + colq;
            float b0 = __ldg(bias + col);
            float b1 = __ldg(bias + col + 1);
#pragma unroll
            for (int rp = 0; rp < 2; rp++) {
                int row = row0 + rp * 8;
                if (row < N) {
                    int i0 = am * 16 + an * 4 + rp * 2;
                    uint32_t bit0 = (kmask >> i0) & 1u;
                    uint32_t bit1 = (kmask >> (i0 + 1)) & 1u;
                    float y0 = acc[am][an][rp * 2 + 0] + b0;
                    float y1 = acc[am][an][rp * 2 + 1] + b1;
                    float2 v;
                    v.x = bit0 ? y0 * 1.25f : 0.0f;
                    v.y = bit1 ? y1 * 1.25f : 0.0f;
                    *(float2*)(out + (size_t)row * 128 + col) = v;
                }
            }
        }
    }
}

// ===========================================================================
// Launch: ONE grouped kernel; 2 blocks (col halves) per 128-row tile.
// Inputs interleaved (x_t, W_t, b_t) x 8; detect layout.
// ===========================================================================
static const int C_TAB[8] = {128, 256, 64, 128, 192, 96, 160, 128};

extern "C" void kernel_launch(void* const* d_in, const int* in_sizes, int n_in,
                              void* d_out, int out_size)
{
    (void)n_in; (void)out_size;
    const bool interleaved = (in_sizes[1] == 128 * C_TAB[0]);

    Params p;
    size_t off = 0;
    int bstart = 0;
    for (int t = 0; t < 8; t++) {
        const int C = C_TAB[t];
        const int xi = interleaved ? (3 * t)     : t;
        const int wi = interleaved ? (3 * t + 1) : (8 + t);
        const int bi = interleaved ? (3 * t + 2) : (16 + t);
        const int N  = in_sizes[xi] / C;

        uint32_t fk0, fk1;
        threefry2x32_host(0u, 42u, 0u, (uint32_t)t, fk0, fk1);

        p.e[t].x      = (const float*)d_in[xi];
        p.e[t].W      = (const float*)d_in[wi];
        p.e[t].bias   = (const float*)d_in[bi];
        p.e[t].out    = (float*)d_out + off;
        p.e[t].N      = N;
        p.e[t].C      = C;
        p.e[t].ksteps = C / 32;
        p.e[t].bstart = bstart;
        p.e[t].k0     = fk0;
        p.e[t].k1     = fk1;

        bstart += 2 * ((N + 127) / 128);
        off += (size_t)N * 128;
    }

    fused_all<<<bstart, 256>>>(p);
}

// round 14
// speedup vs baseline: 1.1764x; 1.0992x over previous
#include <cuda_runtime.h>
#include <stdint.h>

// ===========================================================================
// JAX threefry2x32 (exact)
// ===========================================================================
static void threefry2x32_host(
    uint32_t k0, uint32_t k1, uint32_t x0, uint32_t x1,
    uint32_t& o0, uint32_t& o1)
{
    uint32_t ks2 = k0 ^ k1 ^ 0x1BD11BDAu;
    x0 += k0; x1 += k1;
#define TF_RNDH(R) { x0 += x1; x1 = (x1 << (R)) | (x1 >> (32 - (R))); x1 ^= x0; }
    TF_RNDH(13) TF_RNDH(15) TF_RNDH(26) TF_RNDH(6)   x0 += k1;  x1 += ks2 + 1u;
    TF_RNDH(17) TF_RNDH(29) TF_RNDH(16) TF_RNDH(24)  x0 += ks2; x1 += k0  + 2u;
    TF_RNDH(13) TF_RNDH(15) TF_RNDH(26) TF_RNDH(6)   x0 += k0;  x1 += k1  + 3u;
    TF_RNDH(17) TF_RNDH(29) TF_RNDH(16) TF_RNDH(24)  x0 += k1;  x1 += ks2 + 4u;
    TF_RNDH(13) TF_RNDH(15) TF_RNDH(26) TF_RNDH(6)   x0 += ks2; x1 += k0  + 5u;
#undef TF_RNDH
    o0 = x0; o1 = x1;
}

// keep-decision for flat element e: partitionable threefry counter (0, e),
// XOR-fold, uniform<0.8f as EXACT integer compare: bits < 0xCCCCCE00 (R9-verified)
__device__ __forceinline__ uint32_t tf_keep(uint32_t k0, uint32_t k1, uint32_t ks2,
                                            uint32_t e)
{
    uint32_t x0 = k0, x1 = e + k1;
#define TF_RND(R) { x0 += x1; x1 = __funnelshift_l(x1, x1, R); x1 ^= x0; }
    TF_RND(13) TF_RND(15) TF_RND(26) TF_RND(6)   x0 += k1;  x1 += ks2 + 1u;
    TF_RND(17) TF_RND(29) TF_RND(16) TF_RND(24)  x0 += ks2; x1 += k0  + 2u;
    TF_RND(13) TF_RND(15) TF_RND(26) TF_RND(6)   x0 += k0;  x1 += k1  + 3u;
    TF_RND(17) TF_RND(29) TF_RND(16) TF_RND(24)  x0 += k1;  x1 += ks2 + 4u;
    TF_RND(13) TF_RND(15) TF_RND(26) TF_RND(6)   x0 += ks2; x1 += k0  + 5u;
#undef TF_RND
    return ((x0 ^ x1) < 0xCCCCCE00u) ? 1u : 0u;
}

// ===========================================================================
// Primitives (baseline PTX — valid on compute_103 non-'a')
// ===========================================================================
__device__ __forceinline__ uint32_t smem_u32(const void* p) {
    uint32_t a;
    asm("{ .reg .u64 t; cvta.to.shared.u64 t, %1; cvt.u32.u64 %0, t; }"
        : "=r"(a) : "l"(p));
    return a;
}
__device__ __forceinline__ void ldm4(uint32_t addr,
    uint32_t& r0, uint32_t& r1, uint32_t& r2, uint32_t& r3)
{
    asm volatile("ldmatrix.sync.aligned.m8n8.x4.shared.b16 {%0,%1,%2,%3}, [%4];"
                 : "=r"(r0), "=r"(r1), "=r"(r2), "=r"(r3) : "r"(addr));
}
__device__ __forceinline__ void mma1688(float* d,
    uint32_t a0, uint32_t a1, uint32_t a2, uint32_t a3,
    uint32_t b0, uint32_t b1)
{
    asm volatile(
        "mma.sync.aligned.m16n8k8.row.col.f32.tf32.tf32.f32 "
        "{%0,%1,%2,%3}, {%4,%5,%6,%7}, {%8,%9}, {%0,%1,%2,%3};"
        : "+f"(d[0]), "+f"(d[1]), "+f"(d[2]), "+f"(d[3])
        : "r"(a0), "r"(a1), "r"(a2), "r"(a3), "r"(b0), "r"(b1));
}
// fp32 (as bits) -> tf32, round-to-nearest. Applied to ldmatrix FRAGMENT regs
// (smem holds raw fp32) — arithmetic identical to converting before store.
__device__ __forceinline__ uint32_t tf32r(uint32_t w) {
    uint32_t u;
    asm("cvt.rna.tf32.f32 %0, %1;" : "=r"(u) : "f"(__uint_as_float(w)));
    return u;
}
__device__ __forceinline__ void cvt_frag4(uint32_t* r) {
    r[0] = tf32r(r[0]); r[1] = tf32r(r[1]); r[2] = tf32r(r[2]); r[3] = tf32r(r[3]);
}
// 16B async copy, zero-filled when sz==0 (row out of range)
__device__ __forceinline__ void cp16(uint32_t dst, const void* src, int sz) {
    asm volatile("cp.async.cg.shared.global [%0], [%1], 16, %2;"
                 :: "r"(dst), "l"(src), "r"(sz));
}
#define CP_COMMIT() asm volatile("cp.async.commit_group;")
#define CP_WAIT(n)  asm volatile("cp.async.wait_group %0;" :: "n"(n))

// ===========================================================================
// Grouped fused kernel, ALL 8 types in ONE launch.
// CTA tile 128 rows x 64 cols (col half by block parity), 256 thr, 8 warps,
// warp tile 32x32, 3 CTAs/SM. tf32 GEMM + bias + threefry dropout.
// 2-stage cp.async double buffer: raw fp32 gmem->smem overlaps MMA+RNG;
// tf32 rounding applied on fragment registers (accuracy identical).
// RNG: 32 keep-bits/thread in two fully-unrolled 16-hash bursts (tiles 0/1).
// ===========================================================================
#define RSW 36                        // smem row stride in words (144 B)
#define AW  (128 * RSW)               // A tile words
#define BW  (64 * RSW)                // B tile words
#define STG (AW + BW)                 // words per stage
#define SMEM_BYTES (2 * STG * 4)      // 55296 B

struct Entry {
    const float* x;
    const float* W;
    const float* bias;
    float*       out;
    int N, C, ksteps, bstart;
    uint32_t k0, k1;
};
struct Params { Entry e[8]; };

__global__ __launch_bounds__(256, 3) void fused_all(Params p)
{
    extern __shared__ __align__(16) uint32_t sm[];

    const int bid = blockIdx.x;
    int t = 0;
#pragma unroll
    for (int i = 1; i < 8; i++)
        if (bid >= p.e[i].bstart) t = i;

    const float* __restrict__ x    = p.e[t].x;
    const float* __restrict__ W    = p.e[t].W;
    const float* __restrict__ bias = p.e[t].bias;
    float*       __restrict__ out  = p.e[t].out;
    const int N      = p.e[t].N;
    const int C      = p.e[t].C;
    const int ksteps = p.e[t].ksteps;
    const uint32_t k0 = p.e[t].k0, k1 = p.e[t].k1;
    const uint32_t ks2 = k0 ^ k1 ^ 0x1BD11BDAu;

    const int local = bid - p.e[t].bstart;
    const int base  = (local >> 1) * 128;
    const int colh  = (local & 1) * 64;

    const int tid  = threadIdx.x;
    const int lane = tid & 31;
    const int warp = tid >> 5;
    const int wm   = warp & 3;
    const int wn   = warp >> 2;

    const uint32_t uS = smem_u32(sm);

    const int r16  = lane & 15;
    const int hc16 = (lane >> 4) << 4;
    const int rowq = lane >> 2;
    const int colq = (lane & 3) * 2;
    const int colbase = colh + wn * 32;

    // per-thread copy coords
    const int arow = tid >> 3;        // 0..31 (+32*i) for A; 0..31(+32) for B
    const int aq   = tid & 7;

    float acc[2][4][4];
#pragma unroll
    for (int i = 0; i < 2; i++)
#pragma unroll
        for (int j = 0; j < 4; j++)
#pragma unroll
            for (int q = 0; q < 4; q++) acc[i][j][q] = 0.0f;

    uint32_t kmask = 0;

    // ---- issue tile 0 ----
    {
        const int kb = 0;
#pragma unroll
        for (int it = 0; it < 4; it++) {
            int row = arow + 32 * it;
            int gr  = base + row;
            cp16(uS + (uint32_t)(row * RSW + aq * 4) * 4,
                 x + (long)gr * C + kb + aq * 4, (gr < N) ? 16 : 0);
        }
#pragma unroll
        for (int it = 0; it < 2; it++) {
            int row = arow + 32 * it;
            cp16(uS + (uint32_t)(AW + row * RSW + aq * 4) * 4,
                 W + (long)(colh + row) * C + kb + aq * 4, 16);
        }
        CP_COMMIT();
    }

    for (int kt = 0; kt < ksteps; kt++) {
        const bool hn = (kt + 1) < ksteps;
        if (hn) {
            const int kb = (kt + 1) * 32;
            const uint32_t soff = (uint32_t)(((kt + 1) & 1) * STG) * 4;
#pragma unroll
            for (int it = 0; it < 4; it++) {
                int row = arow + 32 * it;
                int gr  = base + row;
                cp16(uS + soff + (uint32_t)(row * RSW + aq * 4) * 4,
                     x + (long)gr * C + kb + aq * 4, (gr < N) ? 16 : 0);
            }
#pragma unroll
            for (int it = 0; it < 2; it++) {
                int row = arow + 32 * it;
                cp16(uS + soff + (uint32_t)(AW + row * RSW + aq * 4) * 4,
                     W + (long)(colh + row) * C + kb + aq * 4, 16);
            }
            CP_COMMIT();
        }

        // ---- dropout mask burst while copies fly: 16 bits in tiles 0,1 ----
        if (kt < 2) {
            const int am = kt;
            uint32_t m = 0;
#pragma unroll
            for (int ii = 0; ii < 16; ii++) {
                int an = ii >> 2, rp = (ii >> 1) & 1, cp = ii & 1;
                uint32_t row = (uint32_t)(base + wm * 32 + am * 16 + rowq + rp * 8);
                uint32_t col = (uint32_t)(colbase + an * 8 + colq + cp);
                m |= tf_keep(k0, k1, ks2, row * 128u + col) << ii;
            }
            kmask |= m << (kt * 16);
        }

        if (hn) CP_WAIT(1); else CP_WAIT(0);
        __syncthreads();

        // ---- MMA on stage kt&1: 4 chunks of 8 fp32-k ----
        const uint32_t sA = uS + (uint32_t)((kt & 1) * STG) * 4;
        const uint32_t sB = sA + (uint32_t)AW * 4;
#pragma unroll
        for (int c8 = 0; c8 < 4; c8++) {
            const int coff = c8 * 32 + hc16;

            uint32_t ah[2][4];
#pragma unroll
            for (int am = 0; am < 2; am++) {
                ldm4(sA + (uint32_t)((wm * 32 + am * 16 + r16) * 144 + coff),
                     ah[am][0], ah[am][1], ah[am][2], ah[am][3]);
                cvt_frag4(ah[am]);
            }

            uint32_t b[2][4];
#pragma unroll
            for (int pg = 0; pg < 2; pg++) {
                ldm4(sB + (uint32_t)((wn * 32 + pg * 16 + r16) * 144 + coff),
                     b[pg][0], b[pg][1], b[pg][2], b[pg][3]);
                cvt_frag4(b[pg]);
            }

#pragma unroll
            for (int am = 0; am < 2; am++)
#pragma unroll
                for (int pg = 0; pg < 2; pg++) {
                    mma1688(acc[am][2 * pg],     ah[am][0], ah[am][1], ah[am][2], ah[am][3], b[pg][0], b[pg][2]);
                    mma1688(acc[am][2 * pg + 1], ah[am][0], ah[am][1], ah[am][2], ah[am][3], b[pg][1], b[pg][3]);
                }
        }
        __syncthreads();
    }

    // ---- epilogue: bias + masked scale + store ----
#pragma unroll
    for (int am = 0; am < 2; am++) {
        int row0 = base + wm * 32 + am * 16 + rowq;
#pragma unroll
        for (int an = 0; an < 4; an++) {
            int col = colbase + an * 8 + colq;
            float b0 = __ldg(bias + col);
            float b1 = __ldg(bias + col + 1);
#pragma unroll
            for (int rp = 0; rp < 2; rp++) {
                int row = row0 + rp * 8;
                if (row < N) {
                    int i0 = am * 16 + an * 4 + rp * 2;
                    uint32_t bit0 = (kmask >> i0) & 1u;
                    uint32_t bit1 = (kmask >> (i0 + 1)) & 1u;
                    float y0 = acc[am][an][rp * 2 + 0] + b0;
                    float y1 = acc[am][an][rp * 2 + 1] + b1;
                    float2 v;
                    v.x = bit0 ? y0 * 1.25f : 0.0f;
                    v.y = bit1 ? y1 * 1.25f : 0.0f;
                    *(float2*)(out + (size_t)row * 128 + col) = v;
                }
            }
        }
    }
}

// ===========================================================================
// Launch: ONE grouped kernel; 2 blocks (col halves) per 128-row tile.
// ===========================================================================
static const int C_TAB[8] = {128, 256, 64, 128, 192, 96, 160, 128};

extern "C" void kernel_launch(void* const* d_in, const int* in_sizes, int n_in,
                              void* d_out, int out_size)
{
    (void)n_in; (void)out_size;
    const bool interleaved = (in_sizes[1] == 128 * C_TAB[0]);

    static bool attr_set = false;
    if (!attr_set) {
        cudaFuncSetAttribute(fused_all,
                             cudaFuncAttributeMaxDynamicSharedMemorySize, SMEM_BYTES);
        attr_set = true;
    }

    Params p;
    size_t off = 0;
    int bstart = 0;
    for (int t = 0; t < 8; t++) {
        const int C = C_TAB[t];
        const int xi = interleaved ? (3 * t)     : t;
        const int wi = interleaved ? (3 * t + 1) : (8 + t);
        const int bi = interleaved ? (3 * t + 2) : (16 + t);
        const int N  = in_sizes[xi] / C;

        uint32_t fk0, fk1;
        threefry2x32_host(0u, 42u, 0u, (uint32_t)t, fk0, fk1);

        p.e[t].x      = (const float*)d_in[xi];
        p.e[t].W      = (const float*)d_in[wi];
        p.e[t].bias   = (const float*)d_in[bi];
        p.e[t].out    = (float*)d_out + off;
        p.e[t].N      = N;
        p.e[t].C      = C;
        p.e[t].ksteps = C / 32;
        p.e[t].bstart = bstart;
        p.e[t].k0     = fk0;
        p.e[t].k1     = fk1;

        bstart += 2 * ((N + 127) / 128);
        off += (size_t)N * 128;
    }

    fused_all<<<bstart, 256, SMEM_BYTES>>>(p);
}